// round 4
// baseline (speedup 1.0000x reference)
#include <cuda_runtime.h>
#include <cuda_bf16.h>
#include <math.h>

typedef unsigned long long ull;

#define SA 36          // padded k-stride (floats) for GEMM shared tiles
#define HSTR 260       // padded row stride (floats) for recurrence shared state
#define KB_SMEM ((12 + 64) * HSTR * 4)

// ------------------------- device scratch (zero-initialized) ----------------
__device__ float g_GI[2u * 128u * 768u * 64u];   // [dir][w][gaterow768][s]
__device__ float g_WENC[8192u * 512u];           // [(s*128+w)][dir*256+u]
__device__ float g_H[2 * 2 * 64 * 256];          // [pingpong][dir][s][u]
__device__ float g_SSUMP[2][64 * 512];           // partial sent_summ [whalf][s][col]
__device__ float g_SGIP[4 * 64 * 3072];          // kD partials [kc][s][row3072]
__device__ float g_SENT[64 * 1024];              // sentenc [s][2HS]
__device__ float g_FP[8 * 64 * 1024];            // kF1 partials [kc][s][row1024]
__device__ float g_DOC[1024];                    // doc vector (atomic accum)
__device__ volatile unsigned g_flags[128];       // grid barrier flags (monotone)

// ------------------------- helpers ------------------------------------------
__device__ __forceinline__ void fma2(ull& d, ull a, ull b) {
    asm("fma.rn.f32x2 %0, %1, %2, %0;" : "+l"(d) : "l"(a), "l"(b));
}
__device__ __forceinline__ float hsum2(ull v) {
    float lo, hi;
    asm("mov.b64 {%0,%1}, %2;" : "=f"(lo), "=f"(hi) : "l"(v));
    return lo + hi;
}
__device__ __forceinline__ float sigm(float x) { return 1.0f / (1.0f + expf(-x)); }

// Shared 128x64 GEMM tile inner product over a 32-wide K slab.
__device__ __forceinline__ void mm_tile(const float* __restrict__ Wsh,
                                        const float* __restrict__ Xsh,
                                        ull (&acc)[8][4], int tr, int tc) {
#pragma unroll
    for (int kk = 0; kk < 32; kk += 4) {
        ulonglong2 a[8], b[4];
#pragma unroll
        for (int i = 0; i < 8; i++)
            a[i] = *(const ulonglong2*)&Wsh[(tr + 16 * i) * SA + kk];
#pragma unroll
        for (int j = 0; j < 4; j++)
            b[j] = *(const ulonglong2*)&Xsh[(tc * 4 + j) * SA + kk];
#pragma unroll
        for (int i = 0; i < 8; i++)
#pragma unroll
            for (int j = 0; j < 4; j++) {
                fma2(acc[i][j], a[i].x, b[j].x);
                fma2(acc[i][j], a[i].y, b[j].y);
            }
    }
}

// ---------------------------------------------------------------------------
// Kernel A: GI[dir][w][row][s] = sum_d emb[doc[s][w]][d]*wWi[row][d] + biases
// grid (12 row-tiles of 128 over 1536 rows, 128 words), 256 threads.
// ---------------------------------------------------------------------------
__global__ __launch_bounds__(256, 2) void kA(const int* __restrict__ doc,
                                             const float* __restrict__ emb,
                                             const float* __restrict__ wWi,
                                             const float* __restrict__ wbi,
                                             const float* __restrict__ wbh) {
    __shared__ float Wsh[128 * SA];
    __shared__ float Xsh[64 * SA];
    __shared__ int   sidx[64];
    const int t  = threadIdx.x;
    const int R0 = blockIdx.x * 128;
    const int w  = blockIdx.y;
    if (t < 64) sidx[t] = doc[t * 128 + w];

    ull acc[8][4];
#pragma unroll
    for (int i = 0; i < 8; i++)
#pragma unroll
        for (int j = 0; j < 4; j++) acc[i][j] = 0ull;
    const int tr = t & 15, tc = t >> 4;

    for (int k0 = 0; k0 < 256; k0 += 32) {
        __syncthreads();
        for (int i = t; i < 1024; i += 256) {           // 128 rows x 32 k
            int r = i >> 3, kq = i & 7;
            *(float4*)&Wsh[r * SA + kq * 4] =
                *(const float4*)&wWi[(size_t)(R0 + r) * 256 + k0 + kq * 4];
        }
        for (int i = t; i < 512; i += 256) {            // 64 s x 32 d (gather)
            int s = i >> 3, kq = i & 7;
            *(float4*)&Xsh[s * SA + kq * 4] =
                *(const float4*)&emb[(size_t)sidx[s] * 256 + k0 + kq * 4];
        }
        __syncthreads();
        mm_tile(Wsh, Xsh, acc, tr, tc);
    }

#pragma unroll
    for (int i = 0; i < 8; i++) {
        int R   = R0 + tr + 16 * i;
        int dir = R / 768, rr = R % 768;
        float bias = wbi[R] + (rr < 512 ? wbh[R] : 0.0f);   // fold bh into r,z
        size_t base = ((size_t)(dir * 128 + w) * 768 + rr) * 64;
        float4 o;
        o.x = hsum2(acc[i][0]) + bias;
        o.y = hsum2(acc[i][1]) + bias;
        o.z = hsum2(acc[i][2]) + bias;
        o.w = hsum2(acc[i][3]) + bias;
        *(float4*)&g_GI[base + tc * 4] = o;
    }
}

// ---------------------------------------------------------------------------
// Kernel B: persistent word bi-GRU. 128 blocks (dir, 4-unit group), 256 thr.
// Flat flag barrier: one publish + one poll round trip, replay-safe via the
// monotone per-block base read at entry (all flags equal between launches).
// ---------------------------------------------------------------------------
__global__ __launch_bounds__(256, 1) void kB(const float* __restrict__ wWh,
                                             const float* __restrict__ wbh) {
    extern __shared__ float sh[];
    float* Wsh = sh;                 // 12 rows x HSTR
    float* Hsh = sh + 12 * HSTR;     // 64 s x HSTR

    const int t   = threadIdx.x;
    const int b   = blockIdx.x;
    const int dir = b >> 6;
    const int u0  = (b & 63) * 4;
    const unsigned base = g_flags[b];     // own flag: written only by this block

    // resident weight rows: gates r,z,n for this block's 4 units
    for (int i = t; i < 12 * 256; i += 256) {
        int row = i >> 8, k = i & 255;
        int g = row >> 2, ui = row & 3;
        Wsh[row * HSTR + k] = wWh[(size_t)(dir * 768 + g * 256 + u0 + ui) * 256 + k];
    }

    const int s  = t >> 2;
    const int ui = t & 3;
    const int u  = u0 + ui;
    const float bhn = wbh[dir * 768 + 512 + u];
    const ulonglong2* wr = (const ulonglong2*)&Wsh[(0 + ui) * HSTR];
    const ulonglong2* wz = (const ulonglong2*)&Wsh[(4 + ui) * HSTR];
    const ulonglong2* wn = (const ulonglong2*)&Wsh[(8 + ui) * HSTR];

    float h = 0.0f;   // this thread's (s,u) state, carried in register
    __syncthreads();

    for (int w = 0; w < 128; w++) {
        size_t gib = (size_t)(dir * 128 + w) * 768 * 64;
        float gr = g_GI[gib + (size_t)u * 64 + s];
        float gz = g_GI[gib + (size_t)(256 + u) * 64 + s];
        float gn = g_GI[gib + (size_t)(512 + u) * 64 + s];

        // stage full per-direction state into shared (L2-coherent loads)
        if (w == 0) {
            float4 z4 = make_float4(0.f, 0.f, 0.f, 0.f);
            for (int i = t; i < 4096; i += 256) {
                int ss = i >> 6, kq = i & 63;
                *(float4*)&Hsh[ss * HSTR + kq * 4] = z4;
            }
        } else {
            const float4* Hg = (const float4*)(g_H + ((size_t)(w & 1) * 2 + dir) * 64 * 256);
#pragma unroll
            for (int j = 0; j < 16; j++) {
                int i = t + 256 * j;
                int ss = i >> 6, kq = i & 63;
                *(float4*)&Hsh[ss * HSTR + kq * 4] = __ldcg(&Hg[i]);
            }
        }
        __syncthreads();

        ull ar = 0ull, az = 0ull, an = 0ull;
        const ulonglong2* hp = (const ulonglong2*)&Hsh[s * HSTR];
#pragma unroll 8
        for (int kk = 0; kk < 64; kk++) {
            ulonglong2 h2 = hp[kk];
            ulonglong2 r2 = wr[kk];
            ulonglong2 z2 = wz[kk];
            ulonglong2 n2 = wn[kk];
            fma2(ar, h2.x, r2.x); fma2(ar, h2.y, r2.y);
            fma2(az, h2.x, z2.x); fma2(az, h2.y, z2.y);
            fma2(an, h2.x, n2.x); fma2(an, h2.y, n2.y);
        }
        float r = sigm(gr + hsum2(ar));                 // bi_r+bh_r folded in gr
        float z = sigm(gz + hsum2(az));
        float n = tanhf(gn + r * (hsum2(an) + bhn));
        h = (1.0f - z) * n + z * h;

        g_H[(((size_t)((w + 1) & 1) * 2 + dir) * 64 + s) * 256 + u] = h;
        g_WENC[(size_t)(s * 128 + w) * 512 + dir * 256 + u] = h;

        // ---- grid barrier ----
        __threadfence();
        __syncthreads();
        unsigned tgt = base + (unsigned)w + 1u;
        if (t == 0) g_flags[b] = tgt;
        if (t < 128) {
            while (g_flags[t] < tgt) { }
            __threadfence();
        }
        __syncthreads();
    }
}

// ---------------------------------------------------------------------------
// Kernel C: partial sent_summ[wh][s][col] = sum_{w in half} tanh(wenc@waW^T+b)
// grid (4 col-tiles, 2 word-halves, 64 sentences), 256 threads.
// ---------------------------------------------------------------------------
__global__ __launch_bounds__(256, 2) void kC(const float* __restrict__ waW,
                                             const float* __restrict__ wab) {
    __shared__ float Wsh[128 * SA];
    __shared__ float Xsh[64 * SA];
    __shared__ float sred[128 * 16];
    const int t  = threadIdx.x;
    const int ct = blockIdx.x, wh = blockIdx.y, s = blockIdx.z;
    const int R0 = ct * 128;

    ull acc[8][4];
#pragma unroll
    for (int i = 0; i < 8; i++)
#pragma unroll
        for (int j = 0; j < 4; j++) acc[i][j] = 0ull;
    const int tr = t & 15, tc = t >> 4;

    for (int k0 = 0; k0 < 512; k0 += 32) {
        __syncthreads();
        for (int i = t; i < 1024; i += 256) {
            int r = i >> 3, kq = i & 7;
            *(float4*)&Wsh[r * SA + kq * 4] =
                *(const float4*)&waW[(size_t)(R0 + r) * 512 + k0 + kq * 4];
        }
        for (int i = t; i < 512; i += 256) {
            int ws = i >> 3, kq = i & 7;
            *(float4*)&Xsh[ws * SA + kq * 4] =
                *(const float4*)&g_WENC[(size_t)(s * 128 + wh * 64 + ws) * 512 + k0 + kq * 4];
        }
        __syncthreads();
        mm_tile(Wsh, Xsh, acc, tr, tc);
    }

#pragma unroll
    for (int i = 0; i < 8; i++) {
        float bias = wab[R0 + tr + 16 * i];
        float v = 0.0f;
#pragma unroll
        for (int j = 0; j < 4; j++) v += tanhf(hsum2(acc[i][j]) + bias);
        sred[(tr + 16 * i) * 16 + tc] = v;
    }
    __syncthreads();
    if (t < 128) {
        float v = 0.0f;
#pragma unroll
        for (int c = 0; c < 16; c++) v += sred[t * 16 + c];
        g_SSUMP[wh][s * 512 + R0 + t] = v;
    }
}

// ---------------------------------------------------------------------------
// Kernel D: split-K sentence-GRU input gate partials.
// grid (24 row-tiles, 4 K-chunks of 128). Partial [kc][s][row3072], no bias.
// ---------------------------------------------------------------------------
__global__ __launch_bounds__(256, 2) void kD(const float* __restrict__ sWi) {
    __shared__ float Wsh[128 * SA];
    __shared__ float Xsh[64 * SA];
    const int t  = threadIdx.x;
    const int R0 = blockIdx.x * 128;
    const int kc = blockIdx.y;
    const int kb = kc * 128;

    ull acc[8][4];
#pragma unroll
    for (int i = 0; i < 8; i++)
#pragma unroll
        for (int j = 0; j < 4; j++) acc[i][j] = 0ull;
    const int tr = t & 15, tc = t >> 4;

    for (int k0 = kb; k0 < kb + 128; k0 += 32) {
        __syncthreads();
        for (int i = t; i < 1024; i += 256) {
            int r = i >> 3, kq = i & 7;
            *(float4*)&Wsh[r * SA + kq * 4] =
                *(const float4*)&sWi[(size_t)(R0 + r) * 512 + k0 + kq * 4];
        }
        for (int i = t; i < 512; i += 256) {
            int ss = i >> 3, kq = i & 7;
            float4 a = *(const float4*)&g_SSUMP[0][ss * 512 + k0 + kq * 4];
            float4 b = *(const float4*)&g_SSUMP[1][ss * 512 + k0 + kq * 4];
            *(float4*)&Xsh[ss * SA + kq * 4] =
                make_float4(a.x + b.x, a.y + b.y, a.z + b.z, a.w + b.w);
        }
        __syncthreads();
        mm_tile(Wsh, Xsh, acc, tr, tc);
    }

#pragma unroll
    for (int i = 0; i < 8; i++) {
        int R = R0 + tr + 16 * i;
#pragma unroll
        for (int j = 0; j < 4; j++) {
            int s = tc * 4 + j;
            g_SGIP[((size_t)kc * 64 + s) * 3072 + R] = hsum2(acc[i][j]);
        }
    }
}

// ---------------------------------------------------------------------------
// Kernel E: reduce kD partials + biases -> sentence GRU combine (h0 = 0).
// Also zeroes g_DOC for kF2's atomic accumulation.
// ---------------------------------------------------------------------------
__global__ __launch_bounds__(512) void kE(const float* __restrict__ sbi,
                                          const float* __restrict__ sbh) {
    int idx = blockIdx.x * 512 + threadIdx.x;       // 65536
    if (idx < 1024) g_DOC[idx] = 0.0f;
    int u = idx & 511, s = (idx >> 9) & 63, dir = idx >> 15;
    float gr = 0.f, gz = 0.f, gn = 0.f;
#pragma unroll
    for (int kc = 0; kc < 4; kc++) {
        size_t base = ((size_t)kc * 64 + s) * 3072 + dir * 1536;
        gr += g_SGIP[base + u];
        gz += g_SGIP[base + 512 + u];
        gn += g_SGIP[base + 1024 + u];
    }
    int Rr = dir * 1536 + u;
    float r = sigm(gr + sbi[Rr] + sbh[Rr]);
    float z = sigm(gz + sbi[Rr + 512] + sbh[Rr + 512]);
    float n = tanhf(gn + sbi[Rr + 1024] + r * sbh[Rr + 1024]);
    g_SENT[s * 1024 + dir * 512 + u] = (1.0f - z) * n;
}

// ---------------------------------------------------------------------------
// Kernel F1: split-K sentence attention GEMM partials: [kc][s][row1024].
// grid (8 row-tiles, 8 K-chunks of 128).
// ---------------------------------------------------------------------------
__global__ __launch_bounds__(256, 2) void kF1(const float* __restrict__ saW) {
    __shared__ float Wsh[128 * SA];
    __shared__ float Xsh[64 * SA];
    const int t  = threadIdx.x;
    const int R0 = blockIdx.x * 128;
    const int kc = blockIdx.y;
    const int kb = kc * 128;

    ull acc[8][4];
#pragma unroll
    for (int i = 0; i < 8; i++)
#pragma unroll
        for (int j = 0; j < 4; j++) acc[i][j] = 0ull;
    const int tr = t & 15, tc = t >> 4;

    for (int k0 = kb; k0 < kb + 128; k0 += 32) {
        __syncthreads();
        for (int i = t; i < 1024; i += 256) {
            int r = i >> 3, kq = i & 7;
            *(float4*)&Wsh[r * SA + kq * 4] =
                *(const float4*)&saW[(size_t)(R0 + r) * 1024 + k0 + kq * 4];
        }
        for (int i = t; i < 512; i += 256) {
            int ss = i >> 3, kq = i & 7;
            *(float4*)&Xsh[ss * SA + kq * 4] =
                *(const float4*)&g_SENT[ss * 1024 + k0 + kq * 4];
        }
        __syncthreads();
        mm_tile(Wsh, Xsh, acc, tr, tc);
    }

#pragma unroll
    for (int i = 0; i < 8; i++) {
        int R = R0 + tr + 16 * i;
#pragma unroll
        for (int j = 0; j < 4; j++) {
            int s = tc * 4 + j;
            g_FP[((size_t)kc * 64 + s) * 1024 + R] = hsum2(acc[i][j]);
        }
    }
}

// ---------------------------------------------------------------------------
// Kernel F2: reduce kF1 partials over K, tanh+bias, partial s-sum, atomicAdd
// into g_DOC. grid 16 x 256: gid -> (row 0..1023, s-quarter 0..3).
// ---------------------------------------------------------------------------
__global__ __launch_bounds__(256) void kF2(const float* __restrict__ sab) {
    int gid = blockIdx.x * 256 + threadIdx.x;   // 4096
    int row = gid & 1023;
    int sq  = gid >> 10;
    float bias = sab[row];
    float acc = 0.0f;
    for (int s = sq * 16; s < sq * 16 + 16; s++) {
        float v = 0.0f;
#pragma unroll
        for (int kc = 0; kc < 8; kc++)
            v += g_FP[((size_t)kc * 64 + s) * 1024 + row];
        acc += tanhf(v + bias);
    }
    atomicAdd(&g_DOC[row], acc);
}

// ---------------------------------------------------------------------------
// Kernel G: blocks 0..32 write the all-ones attention weights; block 33
// computes logits = doc @ doW^T + dob and writes log_softmax.
// ---------------------------------------------------------------------------
__global__ __launch_bounds__(256) void kG(const float* __restrict__ doW,
                                          const float* __restrict__ dob,
                                          float* __restrict__ out, int out_size) {
    const int t = threadIdx.x;
    if (blockIdx.x < 33) {
        int idx = blockIdx.x * 256 + t;
        if (idx < out_size - 13) out[idx] = 1.0f;
        return;
    }
    __shared__ float red[256];
    __shared__ float lg[13];
    for (int c = 0; c < 13; c++) {
        float v = 0.0f;
        for (int k = t; k < 1024; k += 256) v += g_DOC[k] * doW[c * 1024 + k];
        red[t] = v;
        __syncthreads();
        for (int s2 = 128; s2 > 0; s2 >>= 1) {
            if (t < s2) red[t] += red[t + s2];
            __syncthreads();
        }
        if (t == 0) lg[c] = red[0] + dob[c];
        __syncthreads();
    }
    if (t == 0) {
        float m = lg[0];
        for (int c = 1; c < 13; c++) m = fmaxf(m, lg[c]);
        float sum = 0.0f;
        for (int c = 0; c < 13; c++) sum += expf(lg[c] - m);
        float l = logf(sum);
        int base = out_size - 13;
        for (int c = 0; c < 13; c++) out[base + c] = lg[c] - m - l;
    }
}

// ---------------------------------------------------------------------------
extern "C" void kernel_launch(void* const* d_in, const int* in_sizes, int n_in,
                              void* d_out, int out_size) {
    const int*   doc = (const int*)d_in[0];
    const float* emb = (const float*)d_in[1];
    const float* wWi = (const float*)d_in[2];
    const float* wWh = (const float*)d_in[3];
    const float* wbi = (const float*)d_in[4];
    const float* wbh = (const float*)d_in[5];
    const float* sWi = (const float*)d_in[6];
    const float* sbi = (const float*)d_in[8];
    const float* sbh = (const float*)d_in[9];
    const float* waW = (const float*)d_in[10];
    const float* wab = (const float*)d_in[11];
    const float* saW = (const float*)d_in[13];
    const float* sab = (const float*)d_in[14];
    const float* doW = (const float*)d_in[16];
    const float* dob = (const float*)d_in[17];
    float* out = (float*)d_out;

    cudaFuncSetAttribute(kB, cudaFuncAttributeMaxDynamicSharedMemorySize, KB_SMEM);

    kA<<<dim3(12, 128), 256>>>(doc, emb, wWi, wbi, wbh);
    kB<<<128, 256, KB_SMEM>>>(wWh, wbh);
    kC<<<dim3(4, 2, 64), 256>>>(waW, wab);
    kD<<<dim3(24, 4), 256>>>(sWi);
    kE<<<128, 512>>>(sbi, sbh);
    kF1<<<dim3(8, 8), 256>>>(saW);
    kF2<<<16, 256>>>(sab);
    kG<<<34, 256>>>(doW, dob, out, out_size);
}

// round 6
// speedup vs baseline: 1.6506x; 1.6506x over previous
#include <cuda_runtime.h>
#include <cuda_bf16.h>
#include <math.h>

typedef unsigned long long ull;

#define SA 36          // padded k-stride (floats) for GEMM shared tiles
#define HSTR 260       // padded row stride (floats) for recurrence shared state
#define KB_SMEM ((12 + 64) * HSTR * 4)

// ------------------------- device scratch (zero-initialized) ----------------
__device__ float g_GI[2u * 128u * 768u * 64u];   // [dir][w][gaterow768][s]
__device__ float g_WENC[8192u * 512u];           // [(s*128+w)][dir*256+u]
__device__ float g_H[2 * 2 * 64 * 256];          // [pingpong][dir][s][u]
__device__ float g_SSUMP[2][64 * 512];           // partial sent_summ [whalf][s][col]
__device__ float g_SGIP[4 * 64 * 3072];          // kD partials [kc][s][row3072]
__device__ float g_SENT[64 * 1024];              // sentenc [s][2HS]
__device__ float g_FP[8 * 64 * 1024];            // kF1 partials [kc][s][row1024]
__device__ float g_DOC[1024];                    // doc vector (atomic accum)
__device__ unsigned g_cnt;                       // monotone arrivals (== 128*g_gen idle)
__device__ unsigned g_gen;                       // monotone completed steps

// ------------------------- helpers ------------------------------------------
__device__ __forceinline__ void fma2(ull& d, ull a, ull b) {
    asm("fma.rn.f32x2 %0, %1, %2, %0;" : "+l"(d) : "l"(a), "l"(b));
}
__device__ __forceinline__ float hsum2(ull v) {
    float lo, hi;
    asm("mov.b64 {%0,%1}, %2;" : "=f"(lo), "=f"(hi) : "l"(v));
    return lo + hi;
}
__device__ __forceinline__ float sigm(float x) { return 1.0f / (1.0f + __expf(-x)); }

// Shared 128x64 GEMM tile inner product over a 32-wide K slab.
__device__ __forceinline__ void mm_tile(const float* __restrict__ Wsh,
                                        const float* __restrict__ Xsh,
                                        ull (&acc)[8][4], int tr, int tc) {
#pragma unroll
    for (int kk = 0; kk < 32; kk += 4) {
        ulonglong2 a[8], b[4];
#pragma unroll
        for (int i = 0; i < 8; i++)
            a[i] = *(const ulonglong2*)&Wsh[(tr + 16 * i) * SA + kk];
#pragma unroll
        for (int j = 0; j < 4; j++)
            b[j] = *(const ulonglong2*)&Xsh[(tc * 4 + j) * SA + kk];
#pragma unroll
        for (int i = 0; i < 8; i++)
#pragma unroll
            for (int j = 0; j < 4; j++) {
                fma2(acc[i][j], a[i].x, b[j].x);
                fma2(acc[i][j], a[i].y, b[j].y);
            }
    }
}

// ---------------------------------------------------------------------------
// Kernel A: GI[dir][w][row][s] = sum_d emb[doc[s][w]][d]*wWi[row][d] + biases
// ---------------------------------------------------------------------------
__global__ __launch_bounds__(256, 2) void kA(const int* __restrict__ doc,
                                             const float* __restrict__ emb,
                                             const float* __restrict__ wWi,
                                             const float* __restrict__ wbi,
                                             const float* __restrict__ wbh) {
    __shared__ float Wsh[128 * SA];
    __shared__ float Xsh[64 * SA];
    __shared__ int   sidx[64];
    const int t  = threadIdx.x;
    const int R0 = blockIdx.x * 128;
    const int w  = blockIdx.y;
    if (t < 64) sidx[t] = doc[t * 128 + w];

    ull acc[8][4];
#pragma unroll
    for (int i = 0; i < 8; i++)
#pragma unroll
        for (int j = 0; j < 4; j++) acc[i][j] = 0ull;
    const int tr = t & 15, tc = t >> 4;

    for (int k0 = 0; k0 < 256; k0 += 32) {
        __syncthreads();
        for (int i = t; i < 1024; i += 256) {           // 128 rows x 32 k
            int r = i >> 3, kq = i & 7;
            *(float4*)&Wsh[r * SA + kq * 4] =
                *(const float4*)&wWi[(size_t)(R0 + r) * 256 + k0 + kq * 4];
        }
        for (int i = t; i < 512; i += 256) {            // 64 s x 32 d (gather)
            int s = i >> 3, kq = i & 7;
            *(float4*)&Xsh[s * SA + kq * 4] =
                *(const float4*)&emb[(size_t)sidx[s] * 256 + k0 + kq * 4];
        }
        __syncthreads();
        mm_tile(Wsh, Xsh, acc, tr, tc);
    }

#pragma unroll
    for (int i = 0; i < 8; i++) {
        int R   = R0 + tr + 16 * i;
        int dir = R / 768, rr = R % 768;
        float bias = wbi[R] + (rr < 512 ? wbh[R] : 0.0f);   // fold bh into r,z
        size_t base = ((size_t)(dir * 128 + w) * 768 + rr) * 64;
        float4 o;
        o.x = hsum2(acc[i][0]) + bias;
        o.y = hsum2(acc[i][1]) + bias;
        o.z = hsum2(acc[i][2]) + bias;
        o.w = hsum2(acc[i][3]) + bias;
        *(float4*)&g_GI[base + tc * 4] = o;
    }
}

// ---------------------------------------------------------------------------
// kOnes: write the all-ones attention weights (word_w, sent_w) to out.
// kZero: zero g_DOC for kF2's atomic accumulation.
// (launched at indices 1,2 so kB lands at the profiled launch index 3)
// ---------------------------------------------------------------------------
__global__ __launch_bounds__(256) void kOnes(float* __restrict__ out, int n) {
    int idx = blockIdx.x * 256 + threadIdx.x;
    if (idx < n) out[idx] = 1.0f;
}
__global__ __launch_bounds__(256) void kZero() {
    int idx = threadIdx.x;
#pragma unroll
    for (int i = 0; i < 4; i++) g_DOC[idx + 256 * i] = 0.0f;
}

// ---------------------------------------------------------------------------
// Kernel B: persistent word bi-GRU. 128 blocks (dir, 4-unit group), 256 thr.
// Release/acquire monotone barrier; GI prefetch pipelined across the barrier.
// ---------------------------------------------------------------------------
__global__ __launch_bounds__(256, 1) void kB(const float* __restrict__ wWh,
                                             const float* __restrict__ wbh) {
    extern __shared__ float sh[];
    float* Wsh = sh;                 // 12 rows x HSTR
    float* Hsh = sh + 12 * HSTR;     // 64 s x HSTR

    const int t   = threadIdx.x;
    const int b   = blockIdx.x;
    const int dir = b >> 6;
    const int u0  = (b & 63) * 4;

    unsigned gen0;
    asm volatile("ld.acquire.gpu.global.u32 %0, [%1];" : "=r"(gen0) : "l"(&g_gen));

    // resident weight rows: gates r,z,n for this block's 4 units
    for (int i = t; i < 12 * 256; i += 256) {
        int row = i >> 8, k = i & 255;
        int g = row >> 2, ui = row & 3;
        Wsh[row * HSTR + k] = wWh[(size_t)(dir * 768 + g * 256 + u0 + ui) * 256 + k];
    }

    const int s  = t >> 2;
    const int ui = t & 3;
    const int u  = u0 + ui;
    const float bhn = wbh[dir * 768 + 512 + u];
    const ulonglong2* wr = (const ulonglong2*)&Wsh[(0 + ui) * HSTR];
    const ulonglong2* wz = (const ulonglong2*)&Wsh[(4 + ui) * HSTR];
    const ulonglong2* wn = (const ulonglong2*)&Wsh[(8 + ui) * HSTR];

    float h = 0.0f;   // this thread's (s,u) state, carried in register

    // prefetch GI for step 0
    float gr = g_GI[(size_t)(dir * 128) * 768 * 64 + (size_t)u * 64 + s];
    float gz = g_GI[(size_t)(dir * 128) * 768 * 64 + (size_t)(256 + u) * 64 + s];
    float gn = g_GI[(size_t)(dir * 128) * 768 * 64 + (size_t)(512 + u) * 64 + s];
    __syncthreads();

    for (int w = 0; w < 128; w++) {
        // stage full per-direction state into shared (L2-coherent loads)
        if (w == 0) {
            float4 z4 = make_float4(0.f, 0.f, 0.f, 0.f);
            for (int i = t; i < 4096; i += 256) {
                int ss = i >> 6, kq = i & 63;
                *(float4*)&Hsh[ss * HSTR + kq * 4] = z4;
            }
        } else {
            const float4* Hg = (const float4*)(g_H + ((size_t)(w & 1) * 2 + dir) * 64 * 256);
#pragma unroll
            for (int j = 0; j < 16; j++) {
                int i = t + 256 * j;
                int ss = i >> 6, kq = i & 63;
                *(float4*)&Hsh[ss * HSTR + kq * 4] = __ldcg(&Hg[i]);
            }
        }
        __syncthreads();

        ull ar = 0ull, az = 0ull, an = 0ull;
        const ulonglong2* hp = (const ulonglong2*)&Hsh[s * HSTR];
#pragma unroll 8
        for (int kk = 0; kk < 64; kk++) {
            ulonglong2 h2 = hp[kk];
            ulonglong2 r2 = wr[kk];
            ulonglong2 z2 = wz[kk];
            ulonglong2 n2 = wn[kk];
            fma2(ar, h2.x, r2.x); fma2(ar, h2.y, r2.y);
            fma2(az, h2.x, z2.x); fma2(az, h2.y, z2.y);
            fma2(an, h2.x, n2.x); fma2(an, h2.y, n2.y);
        }
        float r = sigm(gr + hsum2(ar));                 // bi_r+bh_r folded in gr
        float z = sigm(gz + hsum2(az));
        float n = tanhf(gn + r * (hsum2(an) + bhn));
        h = (1.0f - z) * n + z * h;

        g_H[(((size_t)((w + 1) & 1) * 2 + dir) * 64 + s) * 256 + u] = h;
        g_WENC[(size_t)(s * 128 + w) * 512 + dir * 256 + u] = h;

        if (w < 127) {
            // prefetch GI for step w+1 (independent of the barrier)
            size_t gib = (size_t)(dir * 128 + w + 1) * 768 * 64;
            gr = g_GI[gib + (size_t)u * 64 + s];
            gz = g_GI[gib + (size_t)(256 + u) * 64 + s];
            gn = g_GI[gib + (size_t)(512 + u) * 64 + s];

            // ---- grid barrier (release arrive / acquire wait, monotone) ----
            __syncthreads();
            if (t == 0) {
                unsigned stepv = gen0 + (unsigned)w + 1u;
                unsigned old;
                asm volatile("atom.acq_rel.gpu.global.add.u32 %0, [%1], %2;"
                             : "=r"(old) : "l"(&g_cnt), "r"(1u) : "memory");
                if (old + 1u == stepv * 128u) {
                    asm volatile("st.release.gpu.global.u32 [%0], %1;"
                                 :: "l"(&g_gen), "r"(stepv) : "memory");
                } else {
                    unsigned cur;
                    do {
                        asm volatile("ld.acquire.gpu.global.u32 %0, [%1];"
                                     : "=r"(cur) : "l"(&g_gen) : "memory");
                    } while ((int)(cur - stepv) < 0);
                }
            }
            __syncthreads();
        }
    }
}

// ---------------------------------------------------------------------------
// Kernel C: partial sent_summ[wh][s][col] = sum_{w in half} tanh(wenc@waW^T+b)
// ---------------------------------------------------------------------------
__global__ __launch_bounds__(256, 2) void kC(const float* __restrict__ waW,
                                             const float* __restrict__ wab) {
    __shared__ float Wsh[128 * SA];
    __shared__ float Xsh[64 * SA];
    __shared__ float sred[128 * 16];
    const int t  = threadIdx.x;
    const int ct = blockIdx.x, wh = blockIdx.y, s = blockIdx.z;
    const int R0 = ct * 128;

    ull acc[8][4];
#pragma unroll
    for (int i = 0; i < 8; i++)
#pragma unroll
        for (int j = 0; j < 4; j++) acc[i][j] = 0ull;
    const int tr = t & 15, tc = t >> 4;

    for (int k0 = 0; k0 < 512; k0 += 32) {
        __syncthreads();
        for (int i = t; i < 1024; i += 256) {
            int r = i >> 3, kq = i & 7;
            *(float4*)&Wsh[r * SA + kq * 4] =
                *(const float4*)&waW[(size_t)(R0 + r) * 512 + k0 + kq * 4];
        }
        for (int i = t; i < 512; i += 256) {
            int ws = i >> 3, kq = i & 7;
            *(float4*)&Xsh[ws * SA + kq * 4] =
                *(const float4*)&g_WENC[(size_t)(s * 128 + wh * 64 + ws) * 512 + k0 + kq * 4];
        }
        __syncthreads();
        mm_tile(Wsh, Xsh, acc, tr, tc);
    }

#pragma unroll
    for (int i = 0; i < 8; i++) {
        float bias = wab[R0 + tr + 16 * i];
        float v = 0.0f;
#pragma unroll
        for (int j = 0; j < 4; j++) v += tanhf(hsum2(acc[i][j]) + bias);
        sred[(tr + 16 * i) * 16 + tc] = v;
    }
    __syncthreads();
    if (t < 128) {
        float v = 0.0f;
#pragma unroll
        for (int c = 0; c < 16; c++) v += sred[t * 16 + c];
        g_SSUMP[wh][s * 512 + R0 + t] = v;
    }
}

// ---------------------------------------------------------------------------
// Kernel D: split-K sentence-GRU input gate partials. grid (24, 4 K-chunks).
// ---------------------------------------------------------------------------
__global__ __launch_bounds__(256, 2) void kD(const float* __restrict__ sWi) {
    __shared__ float Wsh[128 * SA];
    __shared__ float Xsh[64 * SA];
    const int t  = threadIdx.x;
    const int R0 = blockIdx.x * 128;
    const int kc = blockIdx.y;
    const int kb = kc * 128;

    ull acc[8][4];
#pragma unroll
    for (int i = 0; i < 8; i++)
#pragma unroll
        for (int j = 0; j < 4; j++) acc[i][j] = 0ull;
    const int tr = t & 15, tc = t >> 4;

    for (int k0 = kb; k0 < kb + 128; k0 += 32) {
        __syncthreads();
        for (int i = t; i < 1024; i += 256) {
            int r = i >> 3, kq = i & 7;
            *(float4*)&Wsh[r * SA + kq * 4] =
                *(const float4*)&sWi[(size_t)(R0 + r) * 512 + k0 + kq * 4];
        }
        for (int i = t; i < 512; i += 256) {
            int ss = i >> 3, kq = i & 7;
            float4 a = *(const float4*)&g_SSUMP[0][ss * 512 + k0 + kq * 4];
            float4 b = *(const float4*)&g_SSUMP[1][ss * 512 + k0 + kq * 4];
            *(float4*)&Xsh[ss * SA + kq * 4] =
                make_float4(a.x + b.x, a.y + b.y, a.z + b.z, a.w + b.w);
        }
        __syncthreads();
        mm_tile(Wsh, Xsh, acc, tr, tc);
    }

#pragma unroll
    for (int i = 0; i < 8; i++) {
        int R = R0 + tr + 16 * i;
#pragma unroll
        for (int j = 0; j < 4; j++) {
            int s = tc * 4 + j;
            g_SGIP[((size_t)kc * 64 + s) * 3072 + R] = hsum2(acc[i][j]);
        }
    }
}

// ---------------------------------------------------------------------------
// Kernel E: reduce kD partials + biases -> sentence GRU combine (h0 = 0).
// ---------------------------------------------------------------------------
__global__ __launch_bounds__(512) void kE(const float* __restrict__ sbi,
                                          const float* __restrict__ sbh) {
    int idx = blockIdx.x * 512 + threadIdx.x;       // 65536
    int u = idx & 511, s = (idx >> 9) & 63, dir = idx >> 15;
    float gr = 0.f, gz = 0.f, gn = 0.f;
#pragma unroll
    for (int kc = 0; kc < 4; kc++) {
        size_t base = ((size_t)kc * 64 + s) * 3072 + dir * 1536;
        gr += g_SGIP[base + u];
        gz += g_SGIP[base + 512 + u];
        gn += g_SGIP[base + 1024 + u];
    }
    int Rr = dir * 1536 + u;
    float r = sigm(gr + sbi[Rr] + sbh[Rr]);
    float z = sigm(gz + sbi[Rr + 512] + sbh[Rr + 512]);
    float n = tanhf(gn + sbi[Rr + 1024] + r * sbh[Rr + 1024]);
    g_SENT[s * 1024 + dir * 512 + u] = (1.0f - z) * n;
}

// ---------------------------------------------------------------------------
// Kernel F1: split-K sentence attention GEMM partials. grid (8, 8 K-chunks).
// ---------------------------------------------------------------------------
__global__ __launch_bounds__(256, 2) void kF1(const float* __restrict__ saW) {
    __shared__ float Wsh[128 * SA];
    __shared__ float Xsh[64 * SA];
    const int t  = threadIdx.x;
    const int R0 = blockIdx.x * 128;
    const int kc = blockIdx.y;
    const int kb = kc * 128;

    ull acc[8][4];
#pragma unroll
    for (int i = 0; i < 8; i++)
#pragma unroll
        for (int j = 0; j < 4; j++) acc[i][j] = 0ull;
    const int tr = t & 15, tc = t >> 4;

    for (int k0 = kb; k0 < kb + 128; k0 += 32) {
        __syncthreads();
        for (int i = t; i < 1024; i += 256) {
            int r = i >> 3, kq = i & 7;
            *(float4*)&Wsh[r * SA + kq * 4] =
                *(const float4*)&saW[(size_t)(R0 + r) * 1024 + k0 + kq * 4];
        }
        for (int i = t; i < 512; i += 256) {
            int ss = i >> 3, kq = i & 7;
            *(float4*)&Xsh[ss * SA + kq * 4] =
                *(const float4*)&g_SENT[ss * 1024 + k0 + kq * 4];
        }
        __syncthreads();
        mm_tile(Wsh, Xsh, acc, tr, tc);
    }

#pragma unroll
    for (int i = 0; i < 8; i++) {
        int R = R0 + tr + 16 * i;
#pragma unroll
        for (int j = 0; j < 4; j++) {
            int s = tc * 4 + j;
            g_FP[((size_t)kc * 64 + s) * 1024 + R] = hsum2(acc[i][j]);
        }
    }
}

// ---------------------------------------------------------------------------
// Kernel F2: reduce kF1 partials over K, tanh+bias, partial s-sum, atomicAdd.
// ---------------------------------------------------------------------------
__global__ __launch_bounds__(256) void kF2(const float* __restrict__ sab) {
    int gid = blockIdx.x * 256 + threadIdx.x;   // 4096
    int row = gid & 1023;
    int sq  = gid >> 10;
    float bias = sab[row];
    float acc = 0.0f;
    for (int s = sq * 16; s < sq * 16 + 16; s++) {
        float v = 0.0f;
#pragma unroll
        for (int kc = 0; kc < 8; kc++)
            v += g_FP[((size_t)kc * 64 + s) * 1024 + row];
        acc += tanhf(v + bias);
    }
    atomicAdd(&g_DOC[row], acc);
}

// ---------------------------------------------------------------------------
// Kernel G: logits = doc @ doW^T + dob, then log_softmax. Single block.
// ---------------------------------------------------------------------------
__global__ __launch_bounds__(256) void kG(const float* __restrict__ doW,
                                          const float* __restrict__ dob,
                                          float* __restrict__ out, int out_size) {
    const int t = threadIdx.x;
    __shared__ float red[256];
    __shared__ float lg[13];
    for (int c = 0; c < 13; c++) {
        float v = 0.0f;
        for (int k = t; k < 1024; k += 256) v += g_DOC[k] * doW[c * 1024 + k];
        red[t] = v;
        __syncthreads();
        for (int s2 = 128; s2 > 0; s2 >>= 1) {
            if (t < s2) red[t] += red[t + s2];
            __syncthreads();
        }
        if (t == 0) lg[c] = red[0] + dob[c];
        __syncthreads();
    }
    if (t == 0) {
        float m = lg[0];
        for (int c = 1; c < 13; c++) m = fmaxf(m, lg[c]);
        float sum = 0.0f;
        for (int c = 0; c < 13; c++) sum += expf(lg[c] - m);
        float l = logf(sum);
        int base = out_size - 13;
        for (int c = 0; c < 13; c++) out[base + c] = lg[c] - m - l;
    }
}

// ---------------------------------------------------------------------------
extern "C" void kernel_launch(void* const* d_in, const int* in_sizes, int n_in,
                              void* d_out, int out_size) {
    const int*   doc = (const int*)d_in[0];
    const float* emb = (const float*)d_in[1];
    const float* wWi = (const float*)d_in[2];
    const float* wWh = (const float*)d_in[3];
    const float* wbi = (const float*)d_in[4];
    const float* wbh = (const float*)d_in[5];
    const float* sWi = (const float*)d_in[6];
    const float* sbi = (const float*)d_in[8];
    const float* sbh = (const float*)d_in[9];
    const float* waW = (const float*)d_in[10];
    const float* wab = (const float*)d_in[11];
    const float* saW = (const float*)d_in[13];
    const float* sab = (const float*)d_in[14];
    const float* doW = (const float*)d_in[16];
    const float* dob = (const float*)d_in[17];
    float* out = (float*)d_out;

    cudaFuncSetAttribute(kB, cudaFuncAttributeMaxDynamicSharedMemorySize, KB_SMEM);

    kA<<<dim3(12, 128), 256>>>(doc, emb, wWi, wbi, wbh);   // launch 0
    kOnes<<<33, 256>>>(out, out_size - 13);                // launch 1
    kZero<<<1, 256>>>();                                   // launch 2
    kB<<<128, 256, KB_SMEM>>>(wWh, wbh);                   // launch 3  <- profiled
    kC<<<dim3(4, 2, 64), 256>>>(waW, wab);
    kD<<<dim3(24, 4), 256>>>(sWi);
    kE<<<128, 512>>>(sbi, sbh);
    kF1<<<dim3(8, 8), 256>>>(saW);
    kF2<<<16, 256>>>(sab);
    kG<<<1, 256>>>(doW, dob, out, out_size);
}

// round 7
// speedup vs baseline: 2.0246x; 1.2266x over previous
#include <cuda_runtime.h>
#include <cuda_bf16.h>
#include <math.h>

typedef unsigned long long ull;

#define SA 36          // padded k-stride (floats) for GEMM shared tiles
#define HG 65          // Hsh row pitch in 16B granules (64 data + 1 pad)
#define KB_SMEM (64 * HG * 16)   // 66560 B

// ------------------------- device scratch (zero-initialized) ----------------
__device__ float g_GI[2u * 128u * 768u * 64u];   // [dir][w][gaterow768][s]
__device__ float g_WENC[8192u * 512u];           // [(s*128+w)][dir*256+u]
__device__ float g_H[2 * 2 * 64 * 256];          // [pingpong][dir][s][u]
__device__ float g_SSUMP[2][64 * 512];           // partial sent_summ [whalf][s][col]
__device__ float g_SGIP[4 * 64 * 3072];          // kD partials [kc][s][row3072]
__device__ float g_SENT[64 * 1024];              // sentenc [s][2HS]
__device__ float g_FP[8 * 64 * 1024];            // kF1 partials [kc][s][row1024]
__device__ float g_DOC[1024];                    // doc vector (atomic accum)
__device__ unsigned g_cnt;                       // monotone arrivals
__device__ unsigned g_gen;                       // monotone completed steps

// ------------------------- helpers ------------------------------------------
__device__ __forceinline__ void fma2(ull& d, ull a, ull b) {
    asm("fma.rn.f32x2 %0, %1, %2, %0;" : "+l"(d) : "l"(a), "l"(b));
}
__device__ __forceinline__ float hsum2(ull v) {
    float lo, hi;
    asm("mov.b64 {%0,%1}, %2;" : "=f"(lo), "=f"(hi) : "l"(v));
    return lo + hi;
}
__device__ __forceinline__ float sigm(float x) { return 1.0f / (1.0f + __expf(-x)); }

__device__ __forceinline__ float sel8(const float* f, int k) {
    float v = f[0];
#pragma unroll
    for (int i = 1; i < 8; i++) v = (k == i) ? f[i] : v;
    return v;
}

// Shared 128x64 GEMM tile inner product over a 32-wide K slab.
__device__ __forceinline__ void mm_tile(const float* __restrict__ Wsh,
                                        const float* __restrict__ Xsh,
                                        ull (&acc)[8][4], int tr, int tc) {
#pragma unroll
    for (int kk = 0; kk < 32; kk += 4) {
        ulonglong2 a[8], b[4];
#pragma unroll
        for (int i = 0; i < 8; i++)
            a[i] = *(const ulonglong2*)&Wsh[(tr + 16 * i) * SA + kk];
#pragma unroll
        for (int j = 0; j < 4; j++)
            b[j] = *(const ulonglong2*)&Xsh[(tc * 4 + j) * SA + kk];
#pragma unroll
        for (int i = 0; i < 8; i++)
#pragma unroll
            for (int j = 0; j < 4; j++) {
                fma2(acc[i][j], a[i].x, b[j].x);
                fma2(acc[i][j], a[i].y, b[j].y);
            }
    }
}

// ---------------------------------------------------------------------------
// Kernel A: GI[dir][w][row][s] = sum_d emb[doc[s][w]][d]*wWi[row][d] + biases
// ---------------------------------------------------------------------------
__global__ __launch_bounds__(256, 2) void kA(const int* __restrict__ doc,
                                             const float* __restrict__ emb,
                                             const float* __restrict__ wWi,
                                             const float* __restrict__ wbi,
                                             const float* __restrict__ wbh) {
    __shared__ float Wsh[128 * SA];
    __shared__ float Xsh[64 * SA];
    __shared__ int   sidx[64];
    const int t  = threadIdx.x;
    const int R0 = blockIdx.x * 128;
    const int w  = blockIdx.y;
    if (t < 64) sidx[t] = doc[t * 128 + w];

    ull acc[8][4];
#pragma unroll
    for (int i = 0; i < 8; i++)
#pragma unroll
        for (int j = 0; j < 4; j++) acc[i][j] = 0ull;
    const int tr = t & 15, tc = t >> 4;

    for (int k0 = 0; k0 < 256; k0 += 32) {
        __syncthreads();
        for (int i = t; i < 1024; i += 256) {
            int r = i >> 3, kq = i & 7;
            *(float4*)&Wsh[r * SA + kq * 4] =
                *(const float4*)&wWi[(size_t)(R0 + r) * 256 + k0 + kq * 4];
        }
        for (int i = t; i < 512; i += 256) {
            int s = i >> 3, kq = i & 7;
            *(float4*)&Xsh[s * SA + kq * 4] =
                *(const float4*)&emb[(size_t)sidx[s] * 256 + k0 + kq * 4];
        }
        __syncthreads();
        mm_tile(Wsh, Xsh, acc, tr, tc);
    }

#pragma unroll
    for (int i = 0; i < 8; i++) {
        int R   = R0 + tr + 16 * i;
        int dir = R / 768, rr = R % 768;
        float bias = wbi[R] + (rr < 512 ? wbh[R] : 0.0f);
        size_t base = ((size_t)(dir * 128 + w) * 768 + rr) * 64;
        float4 o;
        o.x = hsum2(acc[i][0]) + bias;
        o.y = hsum2(acc[i][1]) + bias;
        o.z = hsum2(acc[i][2]) + bias;
        o.w = hsum2(acc[i][3]) + bias;
        *(float4*)&g_GI[base + tc * 4] = o;
    }
}

// ---------------------------------------------------------------------------
__global__ __launch_bounds__(256) void kOnes(float* __restrict__ out, int n) {
    int idx = blockIdx.x * 256 + threadIdx.x;
    if (idx < n) out[idx] = 1.0f;
}
__global__ __launch_bounds__(256) void kZero() {
    int idx = threadIdx.x;
#pragma unroll
    for (int i = 0; i < 4; i++) g_DOC[idx + 256 * i] = 0.0f;
}

// ---------------------------------------------------------------------------
// Kernel B: persistent word bi-GRU. 128 blocks (dir, 4-unit group), 256 thr.
// Wh weights live in REGISTERS (step-invariant); only h comes from shared.
// Warp wp: unit ui=wp&3, s-half sh=wp>>2. Lane: sg=l>>3, ks=l&7 (32-k slice).
// Thread: 3 gates x 8 sentences (s = sh*32 + j*4 + sg) over k-slice ks.
// Reduction: 3-round shfl.xor butterfly over ks lanes; each lane then does
// exactly one GRU update for s_upd = sh*32 + ks*4 + sg, carrying h in a reg.
// Hsh layout: row s (pitch HG granules), granule pg = lg ^ ((lg>>3)&7) —
// conflict-free for sequential staging stores AND (ks,kpb) strided reads.
// ---------------------------------------------------------------------------
__global__ __launch_bounds__(256, 1) void kB(const float* __restrict__ wWh,
                                             const float* __restrict__ wbh) {
    extern __shared__ ulonglong2 Hsh[];          // 64 rows x HG granules
    float4* Hsh4 = (float4*)Hsh;

    const int t    = threadIdx.x;
    const int b    = blockIdx.x;
    const int dir  = b >> 6;
    const int u0   = (b & 63) * 4;
    const int wp   = t >> 5;
    const int lane = t & 31;
    const int ui   = wp & 3;
    const int sh   = wp >> 2;
    const int sg   = lane >> 3;
    const int ks   = lane & 7;
    const int u    = u0 + ui;

    unsigned gen0;
    asm volatile("ld.acquire.gpu.global.u32 %0, [%1];" : "=r"(gen0) : "l"(&g_gen));

    // weights into registers: 3 gates x 32 k (this thread's k-slice)
    ull w0[16], w1[16], w2[16];
    {
        const float* base = wWh + (size_t)(dir * 768 + u) * 256 + ks * 32;
#pragma unroll
        for (int p = 0; p < 16; p++) {
            w0[p] = *(const ull*)&base[p * 2];
            w1[p] = *(const ull*)&base[256 * 256 + p * 2];
            w2[p] = *(const ull*)&base[512 * 256 + p * 2];
        }
    }
    const float bhn = wbh[dir * 768 + 512 + u];
    const int s_upd = sh * 32 + ks * 4 + sg;

    // GI prefetch for step 0
    size_t gib = (size_t)(dir * 128) * 768 * 64;
    float gr = g_GI[gib + (size_t)u * 64 + s_upd];
    float gz = g_GI[gib + (size_t)(256 + u) * 64 + s_upd];
    float gn = g_GI[gib + (size_t)(512 + u) * 64 + s_upd];

    // ---- step 0: h = 0 ----
    float h;
    {
        float r = sigm(gr);
        float z = sigm(gz);
        float n = tanhf(gn + r * bhn);
        h = (1.0f - z) * n;
        g_H[((size_t)(1 * 2 + dir) * 64 + s_upd) * 256 + u] = h;
        g_WENC[(size_t)(s_upd * 128 + 0) * 512 + dir * 256 + u] = h;
    }
    // prefetch GI for step 1
    gib = (size_t)(dir * 128 + 1) * 768 * 64;
    gr = g_GI[gib + (size_t)u * 64 + s_upd];
    gz = g_GI[gib + (size_t)(256 + u) * 64 + s_upd];
    gn = g_GI[gib + (size_t)(512 + u) * 64 + s_upd];

    // ---- barrier after step 0 ----
    __syncthreads();
    if (t == 0) {
        unsigned stepv = gen0 + 1u;
        unsigned old;
        asm volatile("atom.acq_rel.gpu.global.add.u32 %0, [%1], %2;"
                     : "=r"(old) : "l"(&g_cnt), "r"(1u) : "memory");
        if (old + 1u == stepv * 128u) {
            asm volatile("st.release.gpu.global.u32 [%0], %1;"
                         :: "l"(&g_gen), "r"(stepv) : "memory");
        } else {
            unsigned cur;
            do {
                asm volatile("ld.acquire.gpu.global.u32 %0, [%1];"
                             : "=r"(cur) : "l"(&g_gen) : "memory");
            } while ((int)(cur - stepv) < 0);
        }
    }
    __syncthreads();

    for (int w = 1; w < 128; w++) {
        // stage per-direction state [s][k] with XOR swizzle
        const float4* Hg = (const float4*)(g_H + ((size_t)(w & 1) * 2 + dir) * 64 * 256);
#pragma unroll
        for (int m = 0; m < 16; m++) {
            int i  = t + 256 * m;
            int s  = i >> 6;
            int lg = i & 63;
            int pg = lg ^ ((lg >> 3) & 7);
            Hsh4[s * HG + pg] = __ldcg(&Hg[i]);
        }
        __syncthreads();

        // 3 gates x 8 sentences over this thread's 32-k slice
        ull a0[8], a1[8], a2[8];
#pragma unroll
        for (int j = 0; j < 8; j++) { a0[j] = 0ull; a1[j] = 0ull; a2[j] = 0ull; }
#pragma unroll
        for (int j = 0; j < 8; j++) {
            const ulonglong2* hp = &Hsh[(sh * 32 + j * 4 + sg) * HG];
#pragma unroll
            for (int kpb = 0; kpb < 8; kpb++) {
                ulonglong2 h2 = hp[(ks * 8 + kpb) ^ ks];
                fma2(a0[j], h2.x, w0[2 * kpb]); fma2(a0[j], h2.y, w0[2 * kpb + 1]);
                fma2(a1[j], h2.x, w1[2 * kpb]); fma2(a1[j], h2.y, w1[2 * kpb + 1]);
                fma2(a2[j], h2.x, w2[2 * kpb]); fma2(a2[j], h2.y, w2[2 * kpb + 1]);
            }
        }

        // butterfly reduce over the 8 ks lanes (lane bits 0..2)
        float f0[8], f1[8], f2[8];
#pragma unroll
        for (int j = 0; j < 8; j++) {
            f0[j] = hsum2(a0[j]); f1[j] = hsum2(a1[j]); f2[j] = hsum2(a2[j]);
        }
#pragma unroll
        for (int mask = 1; mask < 8; mask <<= 1) {
#pragma unroll
            for (int j = 0; j < 8; j++) {
                f0[j] += __shfl_xor_sync(0xffffffffu, f0[j], mask);
                f1[j] += __shfl_xor_sync(0xffffffffu, f1[j], mask);
                f2[j] += __shfl_xor_sync(0xffffffffu, f2[j], mask);
            }
        }

        // this lane's GRU update (sentence j = ks)
        float sr = sel8(f0, ks), sz = sel8(f1, ks), sn = sel8(f2, ks);
        float r = sigm(gr + sr);
        float z = sigm(gz + sz);
        float n = tanhf(gn + r * (sn + bhn));
        h = (1.0f - z) * n + z * h;

        g_H[(((size_t)((w + 1) & 1) * 2 + dir) * 64 + s_upd) * 256 + u] = h;
        g_WENC[(size_t)(s_upd * 128 + w) * 512 + dir * 256 + u] = h;

        if (w < 127) {
            // prefetch GI for step w+1 (barrier-independent)
            gib = (size_t)(dir * 128 + w + 1) * 768 * 64;
            gr = g_GI[gib + (size_t)u * 64 + s_upd];
            gz = g_GI[gib + (size_t)(256 + u) * 64 + s_upd];
            gn = g_GI[gib + (size_t)(512 + u) * 64 + s_upd];

            // ---- grid barrier ----
            __syncthreads();
            if (t == 0) {
                unsigned stepv = gen0 + (unsigned)w + 1u;
                unsigned old;
                asm volatile("atom.acq_rel.gpu.global.add.u32 %0, [%1], %2;"
                             : "=r"(old) : "l"(&g_cnt), "r"(1u) : "memory");
                if (old + 1u == stepv * 128u) {
                    asm volatile("st.release.gpu.global.u32 [%0], %1;"
                                 :: "l"(&g_gen), "r"(stepv) : "memory");
                } else {
                    unsigned cur;
                    do {
                        asm volatile("ld.acquire.gpu.global.u32 %0, [%1];"
                                     : "=r"(cur) : "l"(&g_gen) : "memory");
                    } while ((int)(cur - stepv) < 0);
                }
            }
            __syncthreads();
        }
    }
}

// ---------------------------------------------------------------------------
// Kernel C: partial sent_summ[wh][s][col] = sum_{w in half} tanh(wenc@waW^T+b)
// ---------------------------------------------------------------------------
__global__ __launch_bounds__(256, 2) void kC(const float* __restrict__ waW,
                                             const float* __restrict__ wab) {
    __shared__ float Wsh[128 * SA];
    __shared__ float Xsh[64 * SA];
    __shared__ float sred[128 * 16];
    const int t  = threadIdx.x;
    const int ct = blockIdx.x, wh = blockIdx.y, s = blockIdx.z;
    const int R0 = ct * 128;

    ull acc[8][4];
#pragma unroll
    for (int i = 0; i < 8; i++)
#pragma unroll
        for (int j = 0; j < 4; j++) acc[i][j] = 0ull;
    const int tr = t & 15, tc = t >> 4;

    for (int k0 = 0; k0 < 512; k0 += 32) {
        __syncthreads();
        for (int i = t; i < 1024; i += 256) {
            int r = i >> 3, kq = i & 7;
            *(float4*)&Wsh[r * SA + kq * 4] =
                *(const float4*)&waW[(size_t)(R0 + r) * 512 + k0 + kq * 4];
        }
        for (int i = t; i < 512; i += 256) {
            int ws = i >> 3, kq = i & 7;
            *(float4*)&Xsh[ws * SA + kq * 4] =
                *(const float4*)&g_WENC[(size_t)(s * 128 + wh * 64 + ws) * 512 + k0 + kq * 4];
        }
        __syncthreads();
        mm_tile(Wsh, Xsh, acc, tr, tc);
    }

#pragma unroll
    for (int i = 0; i < 8; i++) {
        float bias = wab[R0 + tr + 16 * i];
        float v = 0.0f;
#pragma unroll
        for (int j = 0; j < 4; j++) v += tanhf(hsum2(acc[i][j]) + bias);
        sred[(tr + 16 * i) * 16 + tc] = v;
    }
    __syncthreads();
    if (t < 128) {
        float v = 0.0f;
#pragma unroll
        for (int c = 0; c < 16; c++) v += sred[t * 16 + c];
        g_SSUMP[wh][s * 512 + R0 + t] = v;
    }
}

// ---------------------------------------------------------------------------
// Kernel D: split-K sentence-GRU input gate partials. grid (24, 4 K-chunks).
// ---------------------------------------------------------------------------
__global__ __launch_bounds__(256, 2) void kD(const float* __restrict__ sWi) {
    __shared__ float Wsh[128 * SA];
    __shared__ float Xsh[64 * SA];
    const int t  = threadIdx.x;
    const int R0 = blockIdx.x * 128;
    const int kc = blockIdx.y;
    const int kb = kc * 128;

    ull acc[8][4];
#pragma unroll
    for (int i = 0; i < 8; i++)
#pragma unroll
        for (int j = 0; j < 4; j++) acc[i][j] = 0ull;
    const int tr = t & 15, tc = t >> 4;

    for (int k0 = kb; k0 < kb + 128; k0 += 32) {
        __syncthreads();
        for (int i = t; i < 1024; i += 256) {
            int r = i >> 3, kq = i & 7;
            *(float4*)&Wsh[r * SA + kq * 4] =
                *(const float4*)&sWi[(size_t)(R0 + r) * 512 + k0 + kq * 4];
        }
        for (int i = t; i < 512; i += 256) {
            int ss = i >> 3, kq = i & 7;
            float4 a = *(const float4*)&g_SSUMP[0][ss * 512 + k0 + kq * 4];
            float4 b = *(const float4*)&g_SSUMP[1][ss * 512 + k0 + kq * 4];
            *(float4*)&Xsh[ss * SA + kq * 4] =
                make_float4(a.x + b.x, a.y + b.y, a.z + b.z, a.w + b.w);
        }
        __syncthreads();
        mm_tile(Wsh, Xsh, acc, tr, tc);
    }

#pragma unroll
    for (int i = 0; i < 8; i++) {
        int R = R0 + tr + 16 * i;
#pragma unroll
        for (int j = 0; j < 4; j++) {
            int s = tc * 4 + j;
            g_SGIP[((size_t)kc * 64 + s) * 3072 + R] = hsum2(acc[i][j]);
        }
    }
}

// ---------------------------------------------------------------------------
// Kernel E: reduce kD partials + biases -> sentence GRU combine (h0 = 0).
// ---------------------------------------------------------------------------
__global__ __launch_bounds__(512) void kE(const float* __restrict__ sbi,
                                          const float* __restrict__ sbh) {
    int idx = blockIdx.x * 512 + threadIdx.x;       // 65536
    int u = idx & 511, s = (idx >> 9) & 63, dir = idx >> 15;
    float gr = 0.f, gz = 0.f, gn = 0.f;
#pragma unroll
    for (int kc = 0; kc < 4; kc++) {
        size_t base = ((size_t)kc * 64 + s) * 3072 + dir * 1536;
        gr += g_SGIP[base + u];
        gz += g_SGIP[base + 512 + u];
        gn += g_SGIP[base + 1024 + u];
    }
    int Rr = dir * 1536 + u;
    float r = sigm(gr + sbi[Rr] + sbh[Rr]);
    float z = sigm(gz + sbi[Rr + 512] + sbh[Rr + 512]);
    float n = tanhf(gn + sbi[Rr + 1024] + r * sbh[Rr + 1024]);
    g_SENT[s * 1024 + dir * 512 + u] = (1.0f - z) * n;
}

// ---------------------------------------------------------------------------
// Kernel F1: split-K sentence attention GEMM partials. grid (8, 8 K-chunks).
// ---------------------------------------------------------------------------
__global__ __launch_bounds__(256, 2) void kF1(const float* __restrict__ saW) {
    __shared__ float Wsh[128 * SA];
    __shared__ float Xsh[64 * SA];
    const int t  = threadIdx.x;
    const int R0 = blockIdx.x * 128;
    const int kc = blockIdx.y;
    const int kb = kc * 128;

    ull acc[8][4];
#pragma unroll
    for (int i = 0; i < 8; i++)
#pragma unroll
        for (int j = 0; j < 4; j++) acc[i][j] = 0ull;
    const int tr = t & 15, tc = t >> 4;

    for (int k0 = kb; k0 < kb + 128; k0 += 32) {
        __syncthreads();
        for (int i = t; i < 1024; i += 256) {
            int r = i >> 3, kq = i & 7;
            *(float4*)&Wsh[r * SA + kq * 4] =
                *(const float4*)&saW[(size_t)(R0 + r) * 1024 + k0 + kq * 4];
        }
        for (int i = t; i < 512; i += 256) {
            int ss = i >> 3, kq = i & 7;
            *(float4*)&Xsh[ss * SA + kq * 4] =
                *(const float4*)&g_SENT[ss * 1024 + k0 + kq * 4];
        }
        __syncthreads();
        mm_tile(Wsh, Xsh, acc, tr, tc);
    }

#pragma unroll
    for (int i = 0; i < 8; i++) {
        int R = R0 + tr + 16 * i;
#pragma unroll
        for (int j = 0; j < 4; j++) {
            int s = tc * 4 + j;
            g_FP[((size_t)kc * 64 + s) * 1024 + R] = hsum2(acc[i][j]);
        }
    }
}

// ---------------------------------------------------------------------------
// Kernel F2: reduce kF1 partials over K, tanh+bias, partial s-sum, atomicAdd.
// ---------------------------------------------------------------------------
__global__ __launch_bounds__(256) void kF2(const float* __restrict__ sab) {
    int gid = blockIdx.x * 256 + threadIdx.x;   // 4096
    int row = gid & 1023;
    int sq  = gid >> 10;
    float bias = sab[row];
    float acc = 0.0f;
    for (int s = sq * 16; s < sq * 16 + 16; s++) {
        float v = 0.0f;
#pragma unroll
        for (int kc = 0; kc < 8; kc++)
            v += g_FP[((size_t)kc * 64 + s) * 1024 + row];
        acc += tanhf(v + bias);
    }
    atomicAdd(&g_DOC[row], acc);
}

// ---------------------------------------------------------------------------
// Kernel G: logits = doc @ doW^T + dob, then log_softmax. Single block.
// ---------------------------------------------------------------------------
__global__ __launch_bounds__(256) void kG(const float* __restrict__ doW,
                                          const float* __restrict__ dob,
                                          float* __restrict__ out, int out_size) {
    const int t = threadIdx.x;
    __shared__ float red[256];
    __shared__ float lg[13];
    for (int c = 0; c < 13; c++) {
        float v = 0.0f;
        for (int k = t; k < 1024; k += 256) v += g_DOC[k] * doW[c * 1024 + k];
        red[t] = v;
        __syncthreads();
        for (int s2 = 128; s2 > 0; s2 >>= 1) {
            if (t < s2) red[t] += red[t + s2];
            __syncthreads();
        }
        if (t == 0) lg[c] = red[0] + dob[c];
        __syncthreads();
    }
    if (t == 0) {
        float m = lg[0];
        for (int c = 1; c < 13; c++) m = fmaxf(m, lg[c]);
        float sum = 0.0f;
        for (int c = 0; c < 13; c++) sum += expf(lg[c] - m);
        float l = logf(sum);
        int base = out_size - 13;
        for (int c = 0; c < 13; c++) out[base + c] = lg[c] - m - l;
    }
}

// ---------------------------------------------------------------------------
extern "C" void kernel_launch(void* const* d_in, const int* in_sizes, int n_in,
                              void* d_out, int out_size) {
    const int*   doc = (const int*)d_in[0];
    const float* emb = (const float*)d_in[1];
    const float* wWi = (const float*)d_in[2];
    const float* wWh = (const float*)d_in[3];
    const float* wbi = (const float*)d_in[4];
    const float* wbh = (const float*)d_in[5];
    const float* sWi = (const float*)d_in[6];
    const float* sbi = (const float*)d_in[8];
    const float* sbh = (const float*)d_in[9];
    const float* waW = (const float*)d_in[10];
    const float* wab = (const float*)d_in[11];
    const float* saW = (const float*)d_in[13];
    const float* sab = (const float*)d_in[14];
    const float* doW = (const float*)d_in[16];
    const float* dob = (const float*)d_in[17];
    float* out = (float*)d_out;

    cudaFuncSetAttribute(kB, cudaFuncAttributeMaxDynamicSharedMemorySize, KB_SMEM);

    kA<<<dim3(12, 128), 256>>>(doc, emb, wWi, wbi, wbh);   // launch 0
    kOnes<<<33, 256>>>(out, out_size - 13);                // launch 1
    kZero<<<1, 256>>>();                                   // launch 2
    kB<<<128, 256, KB_SMEM>>>(wWh, wbh);                   // launch 3  <- profiled
    kC<<<dim3(4, 2, 64), 256>>>(waW, wab);
    kD<<<dim3(24, 4), 256>>>(sWi);
    kE<<<128, 512>>>(sbi, sbh);
    kF1<<<dim3(8, 8), 256>>>(saW);
    kF2<<<16, 256>>>(sab);
    kG<<<1, 256>>>(doW, dob, out, out_size);
}